// round 15
// baseline (speedup 1.0000x reference)
#include <cuda_runtime.h>
#include <cuda_bf16.h>
#include <cuda_fp16.h>
#include <cstdint>

#define S_LEN 2048
#define D_DIM 4096
#define H_Q   32
#define H_KV  8
#define HDIM  128
#define BATCH 2
#define K_DIM 4096

#define QTOT  (BATCH * H_Q * S_LEN * HDIM)
#define KVTOT (BATCH * H_KV * S_LEN * HDIM)

// Scratch (allocation-free rule: __device__ globals)
__device__ float g_Q[QTOT];                    // [B, H, S, HD] fp32 (pre-rope)
__device__ float g_K[KVTOT];
__device__ __half g_V16[KVTOT];                // V fp16 (straight from GEMM)
__device__ __half g_x16[4096 * 4096];
__device__ __half g_wq16[4096 * 4096];
__device__ __half g_wk16[1024 * 4096];
__device__ __half g_wv16[1024 * 4096];
__device__ __half g_wo16[4096 * 4096];
__device__ __half g_Ah[4096 * 4096];           // flash out, fp16
__device__ __nv_bfloat16 g_Qh[QTOT], g_Ql[QTOT];       // split Q (roped+scaled)
__device__ __nv_bfloat16 g_Kh[KVTOT], g_Kl[KVTOT];     // split K (roped)

// ---------------------------------------------------------------------------
// Fused fp32 -> fp16 convert for all 5 arrays in ONE launch
// ---------------------------------------------------------------------------
#define N4_BIG (4096 * 1024)
#define N4_SML (1024 * 1024)

__global__ void f2h_all(const float* __restrict__ x, const float* __restrict__ wq,
                        const float* __restrict__ wk, const float* __restrict__ wv,
                        const float* __restrict__ wo,
                        __half* __restrict__ x16, __half* __restrict__ wq16,
                        __half* __restrict__ wk16, __half* __restrict__ wv16,
                        __half* __restrict__ wo16)
{
    int i = blockIdx.x * blockDim.x + threadIdx.x;
    const float* s;
    __half* d;
    if (i < N4_BIG)                      { s = x;  d = x16; }
    else if (i < 2 * N4_BIG)             { s = wq; d = wq16; i -= N4_BIG; }
    else if (i < 2 * N4_BIG + N4_SML)    { s = wk; d = wk16; i -= 2 * N4_BIG; }
    else if (i < 2 * N4_BIG + 2 * N4_SML){ s = wv; d = wv16; i -= 2 * N4_BIG + N4_SML; }
    else                                 { s = wo; d = wo16; i -= 2 * N4_BIG + 2 * N4_SML; }
    const float4 f = ((const float4*)s)[i];
    __half2 h0 = __floats2half2_rn(f.x, f.y);
    __half2 h1 = __floats2half2_rn(f.z, f.w);
    ((uint2*)d)[i] = make_uint2(*(uint32_t*)&h0, *(uint32_t*)&h1);
}

// ---------------------------------------------------------------------------
// FP16 NT GEMM, cp.async 3-stage, CTA 128x128, 2 CTAs/SM (16 warps).
// 8 warps as 2m x 4n -> warp tile 64x32. BK=64.
// mode 0: fp32 row-major. mode 1: fp32 head-permuted. mode 2: fp16 head-perm.
// ---------------------------------------------------------------------------
#define STG_BYTES (256 * 144)            // 36864
#define NSTG 3
#define GEMM_SMEM (NSTG * STG_BYTES)     // 110592 <= 114688 (2 CTAs/SM)

__device__ __forceinline__ void cp16(uint32_t dst, const void* src) {
    asm volatile("cp.async.ca.shared.global [%0], [%1], 16;"
                 :: "r"(dst), "l"(src));
}
__device__ __forceinline__ void mma_h(float* d, const uint32_t* a,
                                      uint32_t b0, uint32_t b1) {
    asm volatile(
        "mma.sync.aligned.m16n8k16.row.col.f32.f16.f16.f32 "
        "{%0,%1,%2,%3}, {%4,%5,%6,%7}, {%8,%9}, {%0,%1,%2,%3};"
        : "+f"(d[0]), "+f"(d[1]), "+f"(d[2]), "+f"(d[3])
        : "r"(a[0]), "r"(a[1]), "r"(a[2]), "r"(a[3]), "r"(b0), "r"(b1));
}

__device__ __forceinline__ void hgemm_issue(
    uint32_t sdst, const __half* __restrict__ A, const __half* __restrict__ B,
    int bm, int bn, int k0, int tid)
{
    // 2048 x 16B chunks: rows 0..127 = A tile, 128..255 = B tile.
#pragma unroll
    for (int i = 0; i < 4; i++) {
        const int q = tid + (i << 8);
        const int row = q >> 3, j = q & 7;
        cp16(sdst + row * 144 + (j << 4),
             A + (size_t)(bm + row) * K_DIM + k0 + (j << 3));
    }
#pragma unroll
    for (int i = 4; i < 8; i++) {
        const int q = tid + (i << 8);
        const int row = q >> 3, j = q & 7;
        cp16(sdst + row * 144 + (j << 4),
             B + (size_t)(bn + row - 128) * K_DIM + k0 + (j << 3));
    }
}

__device__ __forceinline__ void hgemm_body(
    const __half* __restrict__ A, const __half* __restrict__ B,
    float* __restrict__ C, int bm, int bn, int N, int mode, int HC)
{
    extern __shared__ char gsm[];
    const uint32_t sbase = (uint32_t)__cvta_generic_to_shared(gsm);
    const int tid = threadIdx.x;

    const int wid = tid >> 5, lane = tid & 31;
    const int wm = (wid >> 2) << 6;   // 0 or 64
    const int wn = (wid & 3) << 5;    // 0,32,64,96
    const int g = lane >> 2;
    const int c = lane & 3;

    float acc[4][4][4];
#pragma unroll
    for (int mt = 0; mt < 4; mt++)
#pragma unroll
        for (int nt = 0; nt < 4; nt++)
#pragma unroll
            for (int e = 0; e < 4; e++) acc[mt][nt][e] = 0.f;

    hgemm_issue(sbase, A, B, bm, bn, 0, tid);
    asm volatile("cp.async.commit_group;" ::: "memory");
    hgemm_issue(sbase + STG_BYTES, A, B, bm, bn, 64, tid);
    asm volatile("cp.async.commit_group;" ::: "memory");

    const int NST = K_DIM / 64;
    int buf = 0;
    for (int s = 0; s < NST; s++) {
        asm volatile("cp.async.wait_group 1;" ::: "memory");
        __syncthreads();

        const uint32_t* Sw = (const uint32_t*)(gsm + buf * STG_BYTES);
        const uint32_t* Bw = Sw + 128 * 36;
#pragma unroll
        for (int kq = 0; kq < 4; kq++) {
            const int kc = (kq << 3) + c;
            uint32_t af[4][4];
#pragma unroll
            for (int mt = 0; mt < 4; mt++) {
                const int m0 = wm + (mt << 4) + g;
                af[mt][0] = Sw[m0 * 36 + kc];
                af[mt][1] = Sw[(m0 + 8) * 36 + kc];
                af[mt][2] = Sw[m0 * 36 + kc + 4];
                af[mt][3] = Sw[(m0 + 8) * 36 + kc + 4];
            }
#pragma unroll
            for (int nt = 0; nt < 4; nt++) {
                const int n0 = wn + (nt << 3) + g;
                const uint32_t b0 = Bw[n0 * 36 + kc];
                const uint32_t b1 = Bw[n0 * 36 + kc + 4];
#pragma unroll
                for (int mt = 0; mt < 4; mt++)
                    mma_h(acc[mt][nt], af[mt], b0, b1);
            }
        }
        __syncthreads();

        if (s + 2 < NST) {
            const int nb = (buf + 2 >= NSTG) ? buf + 2 - NSTG : buf + 2;
            hgemm_issue(sbase + nb * STG_BYTES, A, B, bm, bn, (s + 2) << 6, tid);
            asm volatile("cp.async.commit_group;" ::: "memory");
        }
        buf = (buf + 1 == NSTG) ? 0 : buf + 1;
    }

#pragma unroll
    for (int mt = 0; mt < 4; mt++) {
#pragma unroll
        for (int nt = 0; nt < 4; nt++) {
            const int row = bm + wm + (mt << 4) + g;
            const int col = bn + wn + (nt << 3) + (c << 1);
            float2 lo = make_float2(acc[mt][nt][0], acc[mt][nt][1]);
            float2 hi = make_float2(acc[mt][nt][2], acc[mt][nt][3]);
            if (mode == 0) {
                *(float2*)&C[(size_t)row * N + col] = lo;
                *(float2*)&C[(size_t)(row + 8) * N + col] = hi;
            } else {
                const int hh = col >> 7, hd = col & (HDIM - 1);
                const int b0 = row >> 11, s0 = row & (S_LEN - 1);
                const int b1 = (row + 8) >> 11, s1 = (row + 8) & (S_LEN - 1);
                const size_t i0 = (((size_t)(b0 * HC + hh)) * S_LEN + s0) * HDIM + hd;
                const size_t i1 = (((size_t)(b1 * HC + hh)) * S_LEN + s1) * HDIM + hd;
                if (mode == 1) {
                    *(float2*)&C[i0] = lo;
                    *(float2*)&C[i1] = hi;
                } else {
                    __half* Ch = (__half*)C;
                    *(__half2*)&Ch[i0] = __floats2half2_rn(lo.x, lo.y);
                    *(__half2*)&Ch[i1] = __floats2half2_rn(hi.x, hi.y);
                }
            }
        }
    }
}

// Fused QKV: 48 n-tiles (32 Q | 8 K | 8 V) x 32 m-tiles = 1536 CTAs.
__global__ __launch_bounds__(256, 2)
void qkv_gemm(const __half* __restrict__ x16,
              const __half* __restrict__ wq16, const __half* __restrict__ wk16,
              const __half* __restrict__ wv16,
              float* __restrict__ Q, float* __restrict__ K, __half* __restrict__ V16)
{
    const int nt = blockIdx.x;
    const int bm = blockIdx.y << 7;
    const __half* B;
    float* C;
    int mode, HC, bn;
    if (nt < 32)      { B = wq16; C = Q;           mode = 1; HC = H_Q;  bn = nt << 7; }
    else if (nt < 40) { B = wk16; C = K;           mode = 1; HC = H_KV; bn = (nt - 32) << 7; }
    else              { B = wv16; C = (float*)V16; mode = 2; HC = H_KV; bn = (nt - 40) << 7; }
    hgemm_body(x16, B, C, bm, bn, 0, mode, HC);
}

// Output projection
__global__ __launch_bounds__(256, 2)
void o_gemm(const __half* __restrict__ A, const __half* __restrict__ B,
            float* __restrict__ C)
{
    hgemm_body(A, B, C, blockIdx.y << 7, blockIdx.x << 7, D_DIM, 0, 0);
}

// ---------------------------------------------------------------------------
// Split helpers
// ---------------------------------------------------------------------------
__device__ __forceinline__ void bsplit(float x, __nv_bfloat16& h, __nv_bfloat16& l) {
    h = __float2bfloat16(x);
    l = __float2bfloat16(x - __bfloat162float(h));
}

__global__ void rope_split_q(const float* __restrict__ Q,
                             __nv_bfloat16* __restrict__ Qh, __nv_bfloat16* __restrict__ Ql,
                             const float* __restrict__ cosb, const float* __restrict__ sinb,
                             int npairs)
{
    const int i = blockIdx.x * blockDim.x + threadIdx.x;
    if (i >= npairs) return;
    const float scale = 0.08838834764831845f * 1.44269504088896340f;
    const int p = i & 63;
    const int s = (i >> 6) & (S_LEN - 1);
    const float c = cosb[(s << 6) + p];
    const float sn = sinb[(s << 6) + p];
    const float2 v = ((const float2*)Q)[i];
    float2 o;
    o.x = (v.x * c - v.y * sn) * scale;
    o.y = (v.x * sn + v.y * c) * scale;
    __nv_bfloat16 h0, l0, h1, l1;
    bsplit(o.x, h0, l0); bsplit(o.y, h1, l1);
    ((__nv_bfloat162*)Qh)[i] = __nv_bfloat162(h0, h1);
    ((__nv_bfloat162*)Ql)[i] = __nv_bfloat162(l0, l1);
}

__global__ void rope_split_k(const float* __restrict__ K,
                             __nv_bfloat16* __restrict__ Kh, __nv_bfloat16* __restrict__ Kl,
                             const float* __restrict__ cosb, const float* __restrict__ sinb,
                             int npairs)
{
    const int i = blockIdx.x * blockDim.x + threadIdx.x;
    if (i >= npairs) return;
    const int p = i & 63;
    const int s = (i >> 6) & (S_LEN - 1);
    const float c = cosb[(s << 6) + p];
    const float sn = sinb[(s << 6) + p];
    const float2 v = ((const float2*)K)[i];
    float2 o;
    o.x = v.x * c - v.y * sn;
    o.y = v.x * sn + v.y * c;
    __nv_bfloat16 h0, l0, h1, l1;
    bsplit(o.x, h0, l0); bsplit(o.y, h1, l1);
    ((__nv_bfloat162*)Kh)[i] = __nv_bfloat162(h0, h1);
    ((__nv_bfloat162*)Kl)[i] = __nv_bfloat162(l0, l1);
}

// ---------------------------------------------------------------------------
// Flash attention (R14: split-bf16 QK^T with reg-cached Q frags + fp16 PV)
// ---------------------------------------------------------------------------
#define FSTR 136
#define KVS_H (3 * 64 * FSTR)
#define KVS_B (KVS_H * 2)
#define FLASH_SMEM ((2 * 128 * FSTR) * 2 + 2 * KVS_B)

__device__ __forceinline__ void ldsm4(uint32_t* r, const void* p) {
    uint32_t a = (uint32_t)__cvta_generic_to_shared(p);
    asm volatile("ldmatrix.sync.aligned.m8n8.x4.shared.b16 {%0,%1,%2,%3}, [%4];"
                 : "=r"(r[0]), "=r"(r[1]), "=r"(r[2]), "=r"(r[3]) : "r"(a));
}
__device__ __forceinline__ void ldsm4t(uint32_t* r, const void* p) {
    uint32_t a = (uint32_t)__cvta_generic_to_shared(p);
    asm volatile("ldmatrix.sync.aligned.m8n8.x4.trans.shared.b16 {%0,%1,%2,%3}, [%4];"
                 : "=r"(r[0]), "=r"(r[1]), "=r"(r[2]), "=r"(r[3]) : "r"(a));
}
__device__ __forceinline__ void mma_bf16(float* d, const uint32_t* a,
                                         uint32_t b0, uint32_t b1) {
    asm volatile(
        "mma.sync.aligned.m16n8k16.row.col.f32.bf16.bf16.f32 "
        "{%0,%1,%2,%3}, {%4,%5,%6,%7}, {%8,%9}, {%0,%1,%2,%3};"
        : "+f"(d[0]), "+f"(d[1]), "+f"(d[2]), "+f"(d[3])
        : "r"(a[0]), "r"(a[1]), "r"(a[2]), "r"(a[3]), "r"(b0), "r"(b1));
}
__device__ __forceinline__ uint32_t packh2(float a, float b) {
    __half2 t = __floats2half2_rn(a, b);
    return *(uint32_t*)&t;
}

__device__ __forceinline__ void kv_issue(
    uint32_t skv, int bi,
    const __nv_bfloat16* __restrict__ Khg, const __nv_bfloat16* __restrict__ Klg,
    const __half* __restrict__ Vg, int j0, int tid)
{
    const int pr = tid >> 2;
    const int jb = tid & 3;
    const uint32_t dst0 = skv + bi * KVS_B + pr * (FSTR * 2);
    const size_t src0 = (size_t)(j0 + pr) * HDIM;
#pragma unroll
    for (int i = 0; i < 4; i++) {
        const int j = jb + (i << 2);
        cp16(dst0 + (j << 4), Khg + src0 + (j << 3));
        cp16(dst0 + (64 * FSTR * 2) + (j << 4), Klg + src0 + (j << 3));
        cp16(dst0 + (128 * FSTR * 2) + (j << 4), Vg + src0 + (j << 3));
    }
}

__global__ __launch_bounds__(256, 1)
void flash_bf16(const __nv_bfloat16* __restrict__ Qhg, const __nv_bfloat16* __restrict__ Qlg,
                const __nv_bfloat16* __restrict__ Khg, const __nv_bfloat16* __restrict__ Klg,
                const __half* __restrict__ Vg, __half* __restrict__ O)
{
    extern __shared__ __nv_bfloat16 fsm[];
    __nv_bfloat16* Qh = fsm;
    __nv_bfloat16* Ql = Qh + 128 * FSTR;
    __nv_bfloat16* KV = Ql + 128 * FSTR;
    const uint32_t skv = (uint32_t)__cvta_generic_to_shared(KV);

    const int tid = threadIdx.x;
    const int lane = tid & 31;
    const int w = tid >> 5;
    const int g = lane >> 2;
    const int c = lane & 3;
    const int m0 = w << 4;

    const int q0 = (int)(gridDim.x - 1 - blockIdx.x) << 7;
    const int h  = blockIdx.y;
    const int b  = blockIdx.z;
    const int kvh = h >> 2;

    const size_t qbase = (((size_t)(b * H_Q + h)) * S_LEN + q0) * HDIM;
    const size_t kvbase = ((size_t)(b * H_KV + kvh)) * S_LEN * HDIM;
    const __nv_bfloat16* Khb = Khg + kvbase;
    const __nv_bfloat16* Klb = Klg + kvbase;
    const __half* Vb = Vg + kvbase;

    kv_issue(skv, 0, Khb, Klb, Vb, 0, tid);
    asm volatile("cp.async.commit_group;" ::: "memory");

    for (int v = tid; v < 2048; v += 256) {
        const int r = v >> 4, j8 = (v & 15) << 3;
        *(uint4*)&Qh[r * FSTR + j8] = *(const uint4*)(Qhg + qbase + r * HDIM + j8);
        *(uint4*)&Ql[r * FSTR + j8] = *(const uint4*)(Qlg + qbase + r * HDIM + j8);
    }
    __syncthreads();

    const int a_row = m0 + (lane & 15);
    const int a_cofs = (lane >> 4) << 3;
    uint32_t qfh[8][4], qfl[8][4];
#pragma unroll
    for (int ks = 0; ks < 8; ks++) {
        ldsm4(qfh[ks], &Qh[a_row * FSTR + (ks << 4) + a_cofs]);
        ldsm4(qfl[ks], &Ql[a_row * FSTR + (ks << 4) + a_cofs]);
    }

    float m_run[2] = {-1e30f, -1e30f};
    float l_run[2] = {0.f, 0.f};
    float o_acc[16][4];
#pragma unroll
    for (int n = 0; n < 16; n++)
#pragma unroll
        for (int e = 0; e < 4; e++) o_acc[n][e] = 0.f;

    const int b_rofs = (lane & 7) + ((lane >> 4) << 3);
    const int b_cofs = ((lane >> 3) & 1) << 3;
    const int v_rofs = (lane & 7) + (((lane >> 3) & 1) << 3);
    const int v_cofs = (lane >> 4) << 3;

    const int ntiles = (q0 >> 6) + 2;
    for (int t = 0; t < ntiles; t++) {
        const bool more = (t + 1 < ntiles);
        if (more) {
            kv_issue(skv, (t + 1) & 1, Khb, Klb, Vb, (t + 1) << 6, tid);
            asm volatile("cp.async.commit_group;" ::: "memory");
            asm volatile("cp.async.wait_group 1;" ::: "memory");
        } else {
            asm volatile("cp.async.wait_group 0;" ::: "memory");
        }
        __syncthreads();

        const __nv_bfloat16* Khp = KV + (size_t)(t & 1) * KVS_H;
        const __nv_bfloat16* Klp = Khp + 64 * FSTR;
        const __half* Vp = (const __half*)(Khp + 2 * 64 * FSTR);

        float s[8][4];
#pragma unroll
        for (int n = 0; n < 8; n++)
#pragma unroll
            for (int e = 0; e < 4; e++) s[n][e] = 0.f;

#pragma unroll
        for (int ks = 0; ks < 8; ks++) {
#pragma unroll
            for (int jj = 0; jj < 4; jj++) {
                uint32_t kh[4], kl[4];
                const int br = (jj << 4) + b_rofs;
                const int bc = (ks << 4) + b_cofs;
                ldsm4(kh, &Khp[br * FSTR + bc]);
                ldsm4(kl, &Klp[br * FSTR + bc]);
                mma_bf16(s[2 * jj],     qfh[ks], kh[0], kh[1]);
                mma_bf16(s[2 * jj],     qfh[ks], kl[0], kl[1]);
                mma_bf16(s[2 * jj],     qfl[ks], kh[0], kh[1]);
                mma_bf16(s[2 * jj + 1], qfh[ks], kh[2], kh[3]);
                mma_bf16(s[2 * jj + 1], qfh[ks], kl[2], kl[3]);
                mma_bf16(s[2 * jj + 1], qfl[ks], kh[2], kh[3]);
            }
        }

        const int j0 = t << 6;
        if (t >= ntiles - 2) {
            const int r0 = q0 + m0 + g, r1 = r0 + 8;
#pragma unroll
            for (int n = 0; n < 8; n++) {
                const int col = j0 + (n << 3) + (c << 1);
                if (col > r0)     s[n][0] = -1e30f;
                if (col + 1 > r0) s[n][1] = -1e30f;
                if (col > r1)     s[n][2] = -1e30f;
                if (col + 1 > r1) s[n][3] = -1e30f;
            }
        }

        float mx0 = -1e30f, mx1 = -1e30f;
#pragma unroll
        for (int n = 0; n < 8; n++) {
            mx0 = fmaxf(mx0, fmaxf(s[n][0], s[n][1]));
            mx1 = fmaxf(mx1, fmaxf(s[n][2], s[n][3]));
        }
        mx0 = fmaxf(mx0, __shfl_xor_sync(0xffffffffu, mx0, 1));
        mx0 = fmaxf(mx0, __shfl_xor_sync(0xffffffffu, mx0, 2));
        mx1 = fmaxf(mx1, __shfl_xor_sync(0xffffffffu, mx1, 1));
        mx1 = fmaxf(mx1, __shfl_xor_sync(0xffffffffu, mx1, 2));

        const float mn0 = fmaxf(m_run[0], mx0);
        const float mn1 = fmaxf(m_run[1], mx1);
        const float alpha0 = exp2f(m_run[0] - mn0);
        const float alpha1 = exp2f(m_run[1] - mn1);
        m_run[0] = mn0; m_run[1] = mn1;

        float sum0 = 0.f, sum1 = 0.f;
        uint32_t ph[16];
#pragma unroll
        for (int n = 0; n < 8; n++) {
            float p0 = exp2f(s[n][0] - mn0);
            float p1 = exp2f(s[n][1] - mn0);
            float p2 = exp2f(s[n][2] - mn1);
            float p3 = exp2f(s[n][3] - mn1);
            sum0 += p0 + p1; sum1 += p2 + p3;
            ph[2 * n]     = packh2(p0, p1);
            ph[2 * n + 1] = packh2(p2, p3);
        }
        sum0 += __shfl_xor_sync(0xffffffffu, sum0, 1);
        sum0 += __shfl_xor_sync(0xffffffffu, sum0, 2);
        sum1 += __shfl_xor_sync(0xffffffffu, sum1, 1);
        sum1 += __shfl_xor_sync(0xffffffffu, sum1, 2);
        l_run[0] = l_run[0] * alpha0 + sum0;
        l_run[1] = l_run[1] * alpha1 + sum1;

#pragma unroll
        for (int n = 0; n < 16; n++) {
            o_acc[n][0] *= alpha0; o_acc[n][1] *= alpha0;
            o_acc[n][2] *= alpha1; o_acc[n][3] *= alpha1;
        }

#pragma unroll
        for (int kk = 0; kk < 4; kk++) {
            uint32_t pa[4] = {ph[4 * kk], ph[4 * kk + 1], ph[4 * kk + 2], ph[4 * kk + 3]};
#pragma unroll
            for (int jj = 0; jj < 8; jj++) {
                uint32_t vv[4];
                ldsm4t(vv, &Vp[((kk << 4) + v_rofs) * FSTR + (jj << 4) + v_cofs]);
                mma_h(o_acc[2 * jj],     pa, vv[0], vv[1]);
                mma_h(o_acc[2 * jj + 1], pa, vv[2], vv[3]);
            }
        }
        __syncthreads();
    }

    const float inv0 = 1.f / l_run[0];
    const float inv1 = 1.f / l_run[1];
    const int s0 = q0 + m0 + g;
    const int s1 = s0 + 8;
    __half* d0 = O + (((size_t)(b * S_LEN + s0)) * H_Q + h) * HDIM;
    __half* d1 = O + (((size_t)(b * S_LEN + s1)) * H_Q + h) * HDIM;
#pragma unroll
    for (int n = 0; n < 16; n++) {
        const int col = (n << 3) + (c << 1);
        *(__half2*)(d0 + col) = __floats2half2_rn(o_acc[n][0] * inv0, o_acc[n][1] * inv0);
        *(__half2*)(d1 + col) = __floats2half2_rn(o_acc[n][2] * inv1, o_acc[n][3] * inv1);
    }
}

// ---------------------------------------------------------------------------
extern "C" void kernel_launch(void* const* d_in, const int* in_sizes, int n_in,
                              void* d_out, int out_size)
{
    const float* x    = (const float*)d_in[0];
    const float* wq   = (const float*)d_in[1];
    const float* wk   = (const float*)d_in[2];
    const float* wv   = (const float*)d_in[3];
    const float* wo   = (const float*)d_in[4];
    const float* cosb = (const float*)d_in[5];
    const float* sinb = (const float*)d_in[6];
    float* out = (float*)d_out;

    float *Q, *K;
    __half *V16, *x16, *wq16, *wk16, *wv16, *wo16, *Ah;
    __nv_bfloat16 *Qh, *Ql, *Kh, *Kl;
    cudaGetSymbolAddress((void**)&Q, g_Q);
    cudaGetSymbolAddress((void**)&K, g_K);
    cudaGetSymbolAddress((void**)&V16, g_V16);
    cudaGetSymbolAddress((void**)&x16, g_x16);
    cudaGetSymbolAddress((void**)&wq16, g_wq16);
    cudaGetSymbolAddress((void**)&wk16, g_wk16);
    cudaGetSymbolAddress((void**)&wv16, g_wv16);
    cudaGetSymbolAddress((void**)&wo16, g_wo16);
    cudaGetSymbolAddress((void**)&Ah, g_Ah);
    cudaGetSymbolAddress((void**)&Qh, g_Qh);
    cudaGetSymbolAddress((void**)&Ql, g_Ql);
    cudaGetSymbolAddress((void**)&Kh, g_Kh);
    cudaGetSymbolAddress((void**)&Kl, g_Kl);

    const int M = BATCH * S_LEN;   // 4096

    cudaFuncSetAttribute(qkv_gemm, cudaFuncAttributeMaxDynamicSharedMemorySize, GEMM_SMEM);
    cudaFuncSetAttribute(o_gemm, cudaFuncAttributeMaxDynamicSharedMemorySize, GEMM_SMEM);
    cudaFuncSetAttribute(flash_bf16, cudaFuncAttributeMaxDynamicSharedMemorySize, FLASH_SMEM);

    // Convert all inputs/weights to fp16 in one launch
    const int total4 = 3 * N4_BIG + 2 * N4_SML;
    f2h_all<<<(total4 + 255) / 256, 256>>>(x, wq, wk, wv, wo,
                                           x16, wq16, wk16, wv16, wo16);

    // Fused QKV projection (2 CTAs/SM)
    qkv_gemm<<<dim3(48, M / 128), 256, GEMM_SMEM>>>(x16, wq16, wk16, wv16, Q, K, V16);

    // RoPE + bf16 hi/lo pre-split
    const int qpairs = QTOT / 2;
    const int kvpairs = KVTOT / 2;
    rope_split_q<<<(qpairs + 255) / 256, 256>>>(Q, Qh, Ql, cosb, sinb, qpairs);
    rope_split_k<<<(kvpairs + 255) / 256, 256>>>(K, Kh, Kl, cosb, sinb, kvpairs);

    // Flash attention -> fp16 A
    flash_bf16<<<dim3(S_LEN / 128, H_Q, BATCH), 256, FLASH_SMEM>>>(
        Qh, Ql, Kh, Kl, V16, Ah);

    // Output projection (2 CTAs/SM)
    o_gemm<<<dim3(D_DIM / 128, M / 128), 256, GEMM_SMEM>>>(Ah, wo16, out);
}

// round 16
// speedup vs baseline: 1.0544x; 1.0544x over previous
#include <cuda_runtime.h>
#include <cuda_bf16.h>
#include <cuda_fp16.h>
#include <cstdint>

#define S_LEN 2048
#define D_DIM 4096
#define H_Q   32
#define H_KV  8
#define HDIM  128
#define BATCH 2
#define K_DIM 4096

#define QTOT  (BATCH * H_Q * S_LEN * HDIM)
#define KVTOT (BATCH * H_KV * S_LEN * HDIM)

// Scratch (allocation-free rule: __device__ globals)
__device__ float g_Q[QTOT];                    // [B, H, S, HD] fp32 (pre-rope)
__device__ float g_K[KVTOT];
__device__ __half g_V16[KVTOT];                // V fp16 (straight from GEMM)
__device__ __half g_x16[4096 * 4096];
__device__ __half g_wq16[4096 * 4096];
__device__ __half g_wk16[1024 * 4096];
__device__ __half g_wv16[1024 * 4096];
__device__ __half g_wo16[4096 * 4096];
__device__ __half g_Ah[4096 * 4096];           // flash out, fp16
__device__ __nv_bfloat16 g_Qh[QTOT], g_Ql[QTOT];       // split Q (roped+scaled)
__device__ __nv_bfloat16 g_Kh[KVTOT], g_Kl[KVTOT];     // split K (roped)

// ---------------------------------------------------------------------------
// Fused fp32 -> fp16 convert for all 5 arrays in ONE launch
// ---------------------------------------------------------------------------
#define N4_BIG (4096 * 1024)
#define N4_SML (1024 * 1024)

__global__ void f2h_all(const float* __restrict__ x, const float* __restrict__ wq,
                        const float* __restrict__ wk, const float* __restrict__ wv,
                        const float* __restrict__ wo,
                        __half* __restrict__ x16, __half* __restrict__ wq16,
                        __half* __restrict__ wk16, __half* __restrict__ wv16,
                        __half* __restrict__ wo16)
{
    int i = blockIdx.x * blockDim.x + threadIdx.x;
    const float* s;
    __half* d;
    if (i < N4_BIG)                      { s = x;  d = x16; }
    else if (i < 2 * N4_BIG)             { s = wq; d = wq16; i -= N4_BIG; }
    else if (i < 2 * N4_BIG + N4_SML)    { s = wk; d = wk16; i -= 2 * N4_BIG; }
    else if (i < 2 * N4_BIG + 2 * N4_SML){ s = wv; d = wv16; i -= 2 * N4_BIG + N4_SML; }
    else                                 { s = wo; d = wo16; i -= 2 * N4_BIG + 2 * N4_SML; }
    const float4 f = ((const float4*)s)[i];
    __half2 h0 = __floats2half2_rn(f.x, f.y);
    __half2 h1 = __floats2half2_rn(f.z, f.w);
    ((uint2*)d)[i] = make_uint2(*(uint32_t*)&h0, *(uint32_t*)&h1);
}

// ---------------------------------------------------------------------------
// FP16 NT GEMM (R14-proven): CTA 128x256, BK=64, cp.async 3-stage, 1 CTA/SM.
// mode 0: fp32 row-major. mode 1: fp32 head-permuted. mode 2: fp16 head-perm.
// ---------------------------------------------------------------------------
#define STG_BYTES (384 * 144)
#define NSTG 3
#define GEMM_SMEM (NSTG * STG_BYTES)

__device__ __forceinline__ void cp16(uint32_t dst, const void* src) {
    asm volatile("cp.async.ca.shared.global [%0], [%1], 16;"
                 :: "r"(dst), "l"(src));
}
__device__ __forceinline__ void mma_h(float* d, const uint32_t* a,
                                      uint32_t b0, uint32_t b1) {
    asm volatile(
        "mma.sync.aligned.m16n8k16.row.col.f32.f16.f16.f32 "
        "{%0,%1,%2,%3}, {%4,%5,%6,%7}, {%8,%9}, {%0,%1,%2,%3};"
        : "+f"(d[0]), "+f"(d[1]), "+f"(d[2]), "+f"(d[3])
        : "r"(a[0]), "r"(a[1]), "r"(a[2]), "r"(a[3]), "r"(b0), "r"(b1));
}

__device__ __forceinline__ void hgemm_issue(
    uint32_t sdst, const __half* __restrict__ A, const __half* __restrict__ B,
    int bm, int bn, int k0, int tid)
{
#pragma unroll
    for (int i = 0; i < 4; i++) {
        const int q = tid + (i << 8);
        const int row = q >> 3, j = q & 7;
        cp16(sdst + row * 144 + (j << 4),
             A + (size_t)(bm + row) * K_DIM + k0 + (j << 3));
    }
#pragma unroll
    for (int i = 4; i < 12; i++) {
        const int q = tid + (i << 8);
        const int row = q >> 3, j = q & 7;
        cp16(sdst + row * 144 + (j << 4),
             B + (size_t)(bn + row - 128) * K_DIM + k0 + (j << 3));
    }
}

__device__ __forceinline__ void hgemm_body(
    const __half* __restrict__ A, const __half* __restrict__ B,
    float* __restrict__ C, int bm, int bn, int N, int mode, int HC)
{
    extern __shared__ char gsm[];
    const uint32_t sbase = (uint32_t)__cvta_generic_to_shared(gsm);
    const int tid = threadIdx.x;

    const int wid = tid >> 5, lane = tid & 31;
    const int wm = (wid >> 2) << 6;
    const int wn = (wid & 3) << 6;
    const int g = lane >> 2;
    const int c = lane & 3;

    float acc[4][8][4];
#pragma unroll
    for (int mt = 0; mt < 4; mt++)
#pragma unroll
        for (int nt = 0; nt < 8; nt++)
#pragma unroll
            for (int e = 0; e < 4; e++) acc[mt][nt][e] = 0.f;

    hgemm_issue(sbase, A, B, bm, bn, 0, tid);
    asm volatile("cp.async.commit_group;" ::: "memory");
    hgemm_issue(sbase + STG_BYTES, A, B, bm, bn, 64, tid);
    asm volatile("cp.async.commit_group;" ::: "memory");

    const int NST = K_DIM / 64;
    int buf = 0;
    for (int s = 0; s < NST; s++) {
        asm volatile("cp.async.wait_group 1;" ::: "memory");
        __syncthreads();

        const uint32_t* Sw = (const uint32_t*)(gsm + buf * STG_BYTES);
        const uint32_t* Bw = Sw + 128 * 36;
#pragma unroll
        for (int kq = 0; kq < 4; kq++) {
            const int kc = (kq << 3) + c;
            uint32_t af[4][4];
#pragma unroll
            for (int mt = 0; mt < 4; mt++) {
                const int m0 = wm + (mt << 4) + g;
                af[mt][0] = Sw[m0 * 36 + kc];
                af[mt][1] = Sw[(m0 + 8) * 36 + kc];
                af[mt][2] = Sw[m0 * 36 + kc + 4];
                af[mt][3] = Sw[(m0 + 8) * 36 + kc + 4];
            }
#pragma unroll
            for (int nt = 0; nt < 8; nt++) {
                const int n0 = wn + (nt << 3) + g;
                const uint32_t b0 = Bw[n0 * 36 + kc];
                const uint32_t b1 = Bw[n0 * 36 + kc + 4];
#pragma unroll
                for (int mt = 0; mt < 4; mt++)
                    mma_h(acc[mt][nt], af[mt], b0, b1);
            }
        }
        __syncthreads();

        if (s + 2 < NST) {
            const int nb = (buf + 2 >= NSTG) ? buf + 2 - NSTG : buf + 2;
            hgemm_issue(sbase + nb * STG_BYTES, A, B, bm, bn, (s + 2) << 6, tid);
            asm volatile("cp.async.commit_group;" ::: "memory");
        }
        buf = (buf + 1 == NSTG) ? 0 : buf + 1;
    }

#pragma unroll
    for (int mt = 0; mt < 4; mt++) {
#pragma unroll
        for (int nt = 0; nt < 8; nt++) {
            const int row = bm + wm + (mt << 4) + g;
            const int col = bn + wn + (nt << 3) + (c << 1);
            float2 lo = make_float2(acc[mt][nt][0], acc[mt][nt][1]);
            float2 hi = make_float2(acc[mt][nt][2], acc[mt][nt][3]);
            if (mode == 0) {
                *(float2*)&C[(size_t)row * N + col] = lo;
                *(float2*)&C[(size_t)(row + 8) * N + col] = hi;
            } else {
                const int hh = col >> 7, hd = col & (HDIM - 1);
                const int b0 = row >> 11, s0 = row & (S_LEN - 1);
                const int b1 = (row + 8) >> 11, s1 = (row + 8) & (S_LEN - 1);
                const size_t i0 = (((size_t)(b0 * HC + hh)) * S_LEN + s0) * HDIM + hd;
                const size_t i1 = (((size_t)(b1 * HC + hh)) * S_LEN + s1) * HDIM + hd;
                if (mode == 1) {
                    *(float2*)&C[i0] = lo;
                    *(float2*)&C[i1] = hi;
                } else {
                    __half* Ch = (__half*)C;
                    *(__half2*)&Ch[i0] = __floats2half2_rn(lo.x, lo.y);
                    *(__half2*)&Ch[i1] = __floats2half2_rn(hi.x, hi.y);
                }
            }
        }
    }
}

// Fused QKV: 24 n-tiles (16 Q | 4 K | 4 V) x 32 m-tiles = 768 CTAs.
__global__ __launch_bounds__(256, 1)
void qkv_gemm(const __half* __restrict__ x16,
              const __half* __restrict__ wq16, const __half* __restrict__ wk16,
              const __half* __restrict__ wv16,
              float* __restrict__ Q, float* __restrict__ K, __half* __restrict__ V16)
{
    const int nt = blockIdx.x;
    const int bm = blockIdx.y << 7;
    const __half* B;
    float* C;
    int mode, HC, bn;
    if (nt < 16)      { B = wq16; C = Q;           mode = 1; HC = H_Q;  bn = nt << 8; }
    else if (nt < 20) { B = wk16; C = K;           mode = 1; HC = H_KV; bn = (nt - 16) << 8; }
    else              { B = wv16; C = (float*)V16; mode = 2; HC = H_KV; bn = (nt - 20) << 8; }
    hgemm_body(x16, B, C, bm, bn, 0, mode, HC);
}

// Output projection
__global__ __launch_bounds__(256, 1)
void o_gemm(const __half* __restrict__ A, const __half* __restrict__ B,
            float* __restrict__ C)
{
    hgemm_body(A, B, C, blockIdx.y << 7, blockIdx.x << 8, D_DIM, 0, 0);
}

// ---------------------------------------------------------------------------
// Fused RoPE + bf16 hi/lo split for Q (first qpairs) and K (rest)
// ---------------------------------------------------------------------------
__device__ __forceinline__ void bsplit(float x, __nv_bfloat16& h, __nv_bfloat16& l) {
    h = __float2bfloat16(x);
    l = __float2bfloat16(x - __bfloat162float(h));
}

__global__ void rope_split_qk(const float* __restrict__ Q, const float* __restrict__ K,
                              __nv_bfloat16* __restrict__ Qh, __nv_bfloat16* __restrict__ Ql,
                              __nv_bfloat16* __restrict__ Kh, __nv_bfloat16* __restrict__ Kl,
                              const float* __restrict__ cosb, const float* __restrict__ sinb,
                              int qpairs, int total)
{
    int i = blockIdx.x * blockDim.x + threadIdx.x;
    if (i >= total) return;
    const float* src = Q;
    __nv_bfloat16 *dh = Qh, *dl = Ql;
    float scale = 0.08838834764831845f * 1.44269504088896340f;
    if (i >= qpairs) {
        src = K; dh = Kh; dl = Kl; scale = 1.f;
        i -= qpairs;
    }
    const int p = i & 63;
    const int s = (i >> 6) & (S_LEN - 1);
    const float c = cosb[(s << 6) + p];
    const float sn = sinb[(s << 6) + p];
    const float2 v = ((const float2*)src)[i];
    float2 o;
    o.x = (v.x * c - v.y * sn) * scale;
    o.y = (v.x * sn + v.y * c) * scale;
    __nv_bfloat16 h0, l0, h1, l1;
    bsplit(o.x, h0, l0); bsplit(o.y, h1, l1);
    ((__nv_bfloat162*)dh)[i] = __nv_bfloat162(h0, h1);
    ((__nv_bfloat162*)dl)[i] = __nv_bfloat162(l0, l1);
}

// ---------------------------------------------------------------------------
// Flash attention (R14: split-bf16 QK^T with reg-cached Q frags + fp16 PV)
// ---------------------------------------------------------------------------
#define FSTR 136
#define KVS_H (3 * 64 * FSTR)
#define KVS_B (KVS_H * 2)
#define FLASH_SMEM ((2 * 128 * FSTR) * 2 + 2 * KVS_B)

__device__ __forceinline__ void ldsm4(uint32_t* r, const void* p) {
    uint32_t a = (uint32_t)__cvta_generic_to_shared(p);
    asm volatile("ldmatrix.sync.aligned.m8n8.x4.shared.b16 {%0,%1,%2,%3}, [%4];"
                 : "=r"(r[0]), "=r"(r[1]), "=r"(r[2]), "=r"(r[3]) : "r"(a));
}
__device__ __forceinline__ void ldsm4t(uint32_t* r, const void* p) {
    uint32_t a = (uint32_t)__cvta_generic_to_shared(p);
    asm volatile("ldmatrix.sync.aligned.m8n8.x4.trans.shared.b16 {%0,%1,%2,%3}, [%4];"
                 : "=r"(r[0]), "=r"(r[1]), "=r"(r[2]), "=r"(r[3]) : "r"(a));
}
__device__ __forceinline__ void mma_bf16(float* d, const uint32_t* a,
                                         uint32_t b0, uint32_t b1) {
    asm volatile(
        "mma.sync.aligned.m16n8k16.row.col.f32.bf16.bf16.f32 "
        "{%0,%1,%2,%3}, {%4,%5,%6,%7}, {%8,%9}, {%0,%1,%2,%3};"
        : "+f"(d[0]), "+f"(d[1]), "+f"(d[2]), "+f"(d[3])
        : "r"(a[0]), "r"(a[1]), "r"(a[2]), "r"(a[3]), "r"(b0), "r"(b1));
}
__device__ __forceinline__ uint32_t packh2(float a, float b) {
    __half2 t = __floats2half2_rn(a, b);
    return *(uint32_t*)&t;
}

__device__ __forceinline__ void kv_issue(
    uint32_t skv, int bi,
    const __nv_bfloat16* __restrict__ Khg, const __nv_bfloat16* __restrict__ Klg,
    const __half* __restrict__ Vg, int j0, int tid)
{
    const int pr = tid >> 2;
    const int jb = tid & 3;
    const uint32_t dst0 = skv + bi * KVS_B + pr * (FSTR * 2);
    const size_t src0 = (size_t)(j0 + pr) * HDIM;
#pragma unroll
    for (int i = 0; i < 4; i++) {
        const int j = jb + (i << 2);
        cp16(dst0 + (j << 4), Khg + src0 + (j << 3));
        cp16(dst0 + (64 * FSTR * 2) + (j << 4), Klg + src0 + (j << 3));
        cp16(dst0 + (128 * FSTR * 2) + (j << 4), Vg + src0 + (j << 3));
    }
}

__global__ __launch_bounds__(256, 1)
void flash_bf16(const __nv_bfloat16* __restrict__ Qhg, const __nv_bfloat16* __restrict__ Qlg,
                const __nv_bfloat16* __restrict__ Khg, const __nv_bfloat16* __restrict__ Klg,
                const __half* __restrict__ Vg, __half* __restrict__ O)
{
    extern __shared__ __nv_bfloat16 fsm[];
    __nv_bfloat16* Qh = fsm;
    __nv_bfloat16* Ql = Qh + 128 * FSTR;
    __nv_bfloat16* KV = Ql + 128 * FSTR;
    const uint32_t skv = (uint32_t)__cvta_generic_to_shared(KV);

    const int tid = threadIdx.x;
    const int lane = tid & 31;
    const int w = tid >> 5;
    const int g = lane >> 2;
    const int c = lane & 3;
    const int m0 = w << 4;

    const int q0 = (int)(gridDim.x - 1 - blockIdx.x) << 7;
    const int h  = blockIdx.y;
    const int b  = blockIdx.z;
    const int kvh = h >> 2;

    const size_t qbase = (((size_t)(b * H_Q + h)) * S_LEN + q0) * HDIM;
    const size_t kvbase = ((size_t)(b * H_KV + kvh)) * S_LEN * HDIM;
    const __nv_bfloat16* Khb = Khg + kvbase;
    const __nv_bfloat16* Klb = Klg + kvbase;
    const __half* Vb = Vg + kvbase;

    kv_issue(skv, 0, Khb, Klb, Vb, 0, tid);
    asm volatile("cp.async.commit_group;" ::: "memory");

    for (int v = tid; v < 2048; v += 256) {
        const int r = v >> 4, j8 = (v & 15) << 3;
        *(uint4*)&Qh[r * FSTR + j8] = *(const uint4*)(Qhg + qbase + r * HDIM + j8);
        *(uint4*)&Ql[r * FSTR + j8] = *(const uint4*)(Qlg + qbase + r * HDIM + j8);
    }
    __syncthreads();

    const int a_row = m0 + (lane & 15);
    const int a_cofs = (lane >> 4) << 3;
    uint32_t qfh[8][4], qfl[8][4];
#pragma unroll
    for (int ks = 0; ks < 8; ks++) {
        ldsm4(qfh[ks], &Qh[a_row * FSTR + (ks << 4) + a_cofs]);
        ldsm4(qfl[ks], &Ql[a_row * FSTR + (ks << 4) + a_cofs]);
    }

    float m_run[2] = {-1e30f, -1e30f};
    float l_run[2] = {0.f, 0.f};
    float o_acc[16][4];
#pragma unroll
    for (int n = 0; n < 16; n++)
#pragma unroll
        for (int e = 0; e < 4; e++) o_acc[n][e] = 0.f;

    const int b_rofs = (lane & 7) + ((lane >> 4) << 3);
    const int b_cofs = ((lane >> 3) & 1) << 3;
    const int v_rofs = (lane & 7) + (((lane >> 3) & 1) << 3);
    const int v_cofs = (lane >> 4) << 3;

    const int ntiles = (q0 >> 6) + 2;
    for (int t = 0; t < ntiles; t++) {
        const bool more = (t + 1 < ntiles);
        if (more) {
            kv_issue(skv, (t + 1) & 1, Khb, Klb, Vb, (t + 1) << 6, tid);
            asm volatile("cp.async.commit_group;" ::: "memory");
            asm volatile("cp.async.wait_group 1;" ::: "memory");
        } else {
            asm volatile("cp.async.wait_group 0;" ::: "memory");
        }
        __syncthreads();

        const __nv_bfloat16* Khp = KV + (size_t)(t & 1) * KVS_H;
        const __nv_bfloat16* Klp = Khp + 64 * FSTR;
        const __half* Vp = (const __half*)(Khp + 2 * 64 * FSTR);

        float s[8][4];
#pragma unroll
        for (int n = 0; n < 8; n++)
#pragma unroll
            for (int e = 0; e < 4; e++) s[n][e] = 0.f;

#pragma unroll
        for (int ks = 0; ks < 8; ks++) {
#pragma unroll
            for (int jj = 0; jj < 4; jj++) {
                uint32_t kh[4], kl[4];
                const int br = (jj << 4) + b_rofs;
                const int bc = (ks << 4) + b_cofs;
                ldsm4(kh, &Khp[br * FSTR + bc]);
                ldsm4(kl, &Klp[br * FSTR + bc]);
                mma_bf16(s[2 * jj],     qfh[ks], kh[0], kh[1]);
                mma_bf16(s[2 * jj],     qfh[ks], kl[0], kl[1]);
                mma_bf16(s[2 * jj],     qfl[ks], kh[0], kh[1]);
                mma_bf16(s[2 * jj + 1], qfh[ks], kh[2], kh[3]);
                mma_bf16(s[2 * jj + 1], qfh[ks], kl[2], kl[3]);
                mma_bf16(s[2 * jj + 1], qfl[ks], kh[2], kh[3]);
            }
        }

        const int j0 = t << 6;
        if (t >= ntiles - 2) {
            const int r0 = q0 + m0 + g, r1 = r0 + 8;
#pragma unroll
            for (int n = 0; n < 8; n++) {
                const int col = j0 + (n << 3) + (c << 1);
                if (col > r0)     s[n][0] = -1e30f;
                if (col + 1 > r0) s[n][1] = -1e30f;
                if (col > r1)     s[n][2] = -1e30f;
                if (col + 1 > r1) s[n][3] = -1e30f;
            }
        }

        float mx0 = -1e30f, mx1 = -1e30f;
#pragma unroll
        for (int n = 0; n < 8; n++) {
            mx0 = fmaxf(mx0, fmaxf(s[n][0], s[n][1]));
            mx1 = fmaxf(mx1, fmaxf(s[n][2], s[n][3]));
        }
        mx0 = fmaxf(mx0, __shfl_xor_sync(0xffffffffu, mx0, 1));
        mx0 = fmaxf(mx0, __shfl_xor_sync(0xffffffffu, mx0, 2));
        mx1 = fmaxf(mx1, __shfl_xor_sync(0xffffffffu, mx1, 1));
        mx1 = fmaxf(mx1, __shfl_xor_sync(0xffffffffu, mx1, 2));

        const float mn0 = fmaxf(m_run[0], mx0);
        const float mn1 = fmaxf(m_run[1], mx1);
        const float alpha0 = exp2f(m_run[0] - mn0);
        const float alpha1 = exp2f(m_run[1] - mn1);
        m_run[0] = mn0; m_run[1] = mn1;

        float sum0 = 0.f, sum1 = 0.f;
        uint32_t ph[16];
#pragma unroll
        for (int n = 0; n < 8; n++) {
            float p0 = exp2f(s[n][0] - mn0);
            float p1 = exp2f(s[n][1] - mn0);
            float p2 = exp2f(s[n][2] - mn1);
            float p3 = exp2f(s[n][3] - mn1);
            sum0 += p0 + p1; sum1 += p2 + p3;
            ph[2 * n]     = packh2(p0, p1);
            ph[2 * n + 1] = packh2(p2, p3);
        }
        sum0 += __shfl_xor_sync(0xffffffffu, sum0, 1);
        sum0 += __shfl_xor_sync(0xffffffffu, sum0, 2);
        sum1 += __shfl_xor_sync(0xffffffffu, sum1, 1);
        sum1 += __shfl_xor_sync(0xffffffffu, sum1, 2);
        l_run[0] = l_run[0] * alpha0 + sum0;
        l_run[1] = l_run[1] * alpha1 + sum1;

#pragma unroll
        for (int n = 0; n < 16; n++) {
            o_acc[n][0] *= alpha0; o_acc[n][1] *= alpha0;
            o_acc[n][2] *= alpha1; o_acc[n][3] *= alpha1;
        }

#pragma unroll
        for (int kk = 0; kk < 4; kk++) {
            uint32_t pa[4] = {ph[4 * kk], ph[4 * kk + 1], ph[4 * kk + 2], ph[4 * kk + 3]};
#pragma unroll
            for (int jj = 0; jj < 8; jj++) {
                uint32_t vv[4];
                ldsm4t(vv, &Vp[((kk << 4) + v_rofs) * FSTR + (jj << 4) + v_cofs]);
                mma_h(o_acc[2 * jj],     pa, vv[0], vv[1]);
                mma_h(o_acc[2 * jj + 1], pa, vv[2], vv[3]);
            }
        }
        __syncthreads();
    }

    const float inv0 = 1.f / l_run[0];
    const float inv1 = 1.f / l_run[1];
    const int s0 = q0 + m0 + g;
    const int s1 = s0 + 8;
    __half* d0 = O + (((size_t)(b * S_LEN + s0)) * H_Q + h) * HDIM;
    __half* d1 = O + (((size_t)(b * S_LEN + s1)) * H_Q + h) * HDIM;
#pragma unroll
    for (int n = 0; n < 16; n++) {
        const int col = (n << 3) + (c << 1);
        *(__half2*)(d0 + col) = __floats2half2_rn(o_acc[n][0] * inv0, o_acc[n][1] * inv0);
        *(__half2*)(d1 + col) = __floats2half2_rn(o_acc[n][2] * inv1, o_acc[n][3] * inv1);
    }
}

// ---------------------------------------------------------------------------
extern "C" void kernel_launch(void* const* d_in, const int* in_sizes, int n_in,
                              void* d_out, int out_size)
{
    const float* x    = (const float*)d_in[0];
    const float* wq   = (const float*)d_in[1];
    const float* wk   = (const float*)d_in[2];
    const float* wv   = (const float*)d_in[3];
    const float* wo   = (const float*)d_in[4];
    const float* cosb = (const float*)d_in[5];
    const float* sinb = (const float*)d_in[6];
    float* out = (float*)d_out;

    float *Q, *K;
    __half *V16, *x16, *wq16, *wk16, *wv16, *wo16, *Ah;
    __nv_bfloat16 *Qh, *Ql, *Kh, *Kl;
    cudaGetSymbolAddress((void**)&Q, g_Q);
    cudaGetSymbolAddress((void**)&K, g_K);
    cudaGetSymbolAddress((void**)&V16, g_V16);
    cudaGetSymbolAddress((void**)&x16, g_x16);
    cudaGetSymbolAddress((void**)&wq16, g_wq16);
    cudaGetSymbolAddress((void**)&wk16, g_wk16);
    cudaGetSymbolAddress((void**)&wv16, g_wv16);
    cudaGetSymbolAddress((void**)&wo16, g_wo16);
    cudaGetSymbolAddress((void**)&Ah, g_Ah);
    cudaGetSymbolAddress((void**)&Qh, g_Qh);
    cudaGetSymbolAddress((void**)&Ql, g_Ql);
    cudaGetSymbolAddress((void**)&Kh, g_Kh);
    cudaGetSymbolAddress((void**)&Kl, g_Kl);

    const int M = BATCH * S_LEN;   // 4096

    cudaFuncSetAttribute(qkv_gemm, cudaFuncAttributeMaxDynamicSharedMemorySize, GEMM_SMEM);
    cudaFuncSetAttribute(o_gemm, cudaFuncAttributeMaxDynamicSharedMemorySize, GEMM_SMEM);
    cudaFuncSetAttribute(flash_bf16, cudaFuncAttributeMaxDynamicSharedMemorySize, FLASH_SMEM);

    // Convert all inputs/weights to fp16 in one launch
    const int total4 = 3 * N4_BIG + 2 * N4_SML;
    f2h_all<<<(total4 + 255) / 256, 256>>>(x, wq, wk, wv, wo,
                                           x16, wq16, wk16, wv16, wo16);

    // Fused QKV projection: 24 x 32 CTAs (128x256 tiles)
    qkv_gemm<<<dim3(24, M / 128), 256, GEMM_SMEM>>>(x16, wq16, wk16, wv16, Q, K, V16);

    // Fused RoPE + bf16 hi/lo pre-split for Q and K
    const int qpairs = QTOT / 2;
    const int kvpairs = KVTOT / 2;
    rope_split_qk<<<(qpairs + kvpairs + 255) / 256, 256>>>(
        Q, K, Qh, Ql, Kh, Kl, cosb, sinb, qpairs, qpairs + kvpairs);

    // Flash attention -> fp16 A
    flash_bf16<<<dim3(S_LEN / 128, H_Q, BATCH), 256, FLASH_SMEM>>>(
        Qh, Ql, Kh, Kl, V16, Ah);

    // Output projection
    o_gemm<<<dim3(D_DIM / 256, M / 128), 256, GEMM_SMEM>>>(Ah, wo16, out);
}